// round 5
// baseline (speedup 1.0000x reference)
#include <cuda_runtime.h>

#define T_ 512
#define K_ 8
#define D_ 8
#define CP_ 28          // D*(D-1)/2
#define ILP 4
#define EPS_ 1e-7f

// ---------------- scratch (static device arrays; no allocation) ----------------
__device__ float g_Q [T_ * K_ * D_ * D_];   // after params_kernel: variance-scaled rotation, [t][k][i][j]
__device__ float g_cq[T_ * K_ * D_];        // -sum_i center_i * Qscaled[i][j]
__device__ float g_nc[T_ * K_ * D_];        // 1/sqrt(2*pi*var)
__device__ float g_w [T_ * K_];             // softmax weights

__device__ __forceinline__ float ex2f(float x) {
    float r; asm("ex2.approx.ftz.f32 %0, %1;" : "=f"(r) : "f"(x)); return r;
}
__device__ __forceinline__ float lg2f(float x) {
    float r; asm("lg2.approx.ftz.f32 %0, %1;" : "=f"(r) : "f"(x)); return r;
}

// Strict-upper-triangular element per the reference's concat([v, v[::-1], 0])->reshape scheme.
// All call sites have compile-time (i,j) after unrolling, so this folds to direct loads.
__device__ __forceinline__ float ut_elem(const float* __restrict__ v, int i, int j) {
    if (j <= i) return 0.f;
    int m = i * 8 + j;
    if (m < 28) return v[m];
    if (m < 56) return v[55 - m];
    return 0.f;
}

// ---------------- kernel 1: Cayley transform, one thread per (t,k) ----------------
// Q = (I-A)(I+A)^{-1}. Using A^T=-A:  Q^T = (I-A)^{-1}(I+A).
// Gauss-Jordan on [N|P], N=I-A, P=I+A; P becomes Q^T. No pivoting needed:
// leading principal minors of I-A equal prod(1+mu^2) >= 1.
__global__ void cayley_kernel(const float* __restrict__ cov) {
    int idx = blockIdx.x * blockDim.x + threadIdx.x;
    if (idx >= T_ * K_) return;
    const float* v = cov + idx * CP_;

    float N[D_][D_], P[D_][D_];
#pragma unroll
    for (int i = 0; i < D_; i++)
#pragma unroll
        for (int j = 0; j < D_; j++) {
            float a = 0.5f * (ut_elem(v, j, i) - ut_elem(v, i, j));   // A[i][j]
            float d = (i == j) ? 1.f : 0.f;
            N[i][j] = d - a;
            P[i][j] = d + a;
        }

#pragma unroll
    for (int c = 0; c < D_; c++) {
        float piv = 1.0f / N[c][c];
#pragma unroll
        for (int j = 0; j < D_; j++) { N[c][j] *= piv; P[c][j] *= piv; }
#pragma unroll
        for (int r = 0; r < D_; r++) {
            if (r == c) continue;
            float f = N[r][c];
#pragma unroll
            for (int j = 0; j < D_; j++) {
                N[r][j] = fmaf(-f, N[c][j], N[r][j]);
                P[r][j] = fmaf(-f, P[c][j], P[r][j]);
            }
        }
    }

    float* qo = g_Q + idx * (D_ * D_);
#pragma unroll
    for (int i = 0; i < D_; i++)
#pragma unroll
        for (int j = 0; j < D_; j++)
            qo[i * D_ + j] = P[j][i];   // Q = (Q^T)^T
}

// ---------------- kernel 2: fold variances/centers into Q, softmax weights ----------------
__global__ void params_kernel(const float* __restrict__ centers,
                              const float* __restrict__ wlog,
                              const float* __restrict__ lvar) {
    int idx = blockIdx.x * blockDim.x + threadIdx.x;
    if (idx >= T_ * K_) return;
    int t = idx >> 3;

    float s[D_];
#pragma unroll
    for (int d = 0; d < D_; d++) {
        float lv  = fminf(fmaxf(lvar[idx * D_ + d], -3.5f), 3.5f);
        float var = expf(lv);
        float inv = expf(-lv);
        // exponent (base 2): -0.5*invvar*log2(e) * xt^2  ==  -(xt*s)^2
        s[d] = sqrtf(0.72134752044448169f * inv);       // 0.5*log2(e) = 0.721347...
        g_nc[idx * D_ + d] = rsqrtf(6.283185307179586f * var);
    }

    float ce[D_];
#pragma unroll
    for (int d = 0; d < D_; d++) ce[d] = centers[idx * D_ + d];

    float* q = g_Q + idx * (D_ * D_);
#pragma unroll
    for (int j = 0; j < D_; j++) {
        float acc = 0.f;
#pragma unroll
        for (int i = 0; i < D_; i++) {
            float qs = q[i * D_ + j] * s[j];
            q[i * D_ + j] = qs;                          // in-place scale
            acc = fmaf(ce[i], qs, acc);
        }
        g_cq[idx * D_ + j] = -acc;
    }

    float num = expf(fminf(fmaxf(wlog[idx], -3.5f), 3.5f));
    float den = 0.f;
#pragma unroll
    for (int k = 0; k < K_; k++)
        den += expf(fminf(fmaxf(wlog[t * K_ + k], -3.5f), 3.5f));
    g_w[idx] = num / den;
}

// ---------------- kernel 3: main evaluation ----------------
// One block per (t, 1024-b-tile). 256 threads, each handles ILP=4 b's so every
// shared-memory param read feeds 4 FMAs (keeps LDS under the MUFU roofline).
__global__ void __launch_bounds__(256) pdf_kernel(const float* __restrict__ x,
                                                  float* __restrict__ out, int B) {
    const int t   = blockIdx.y;
    const int tid = threadIdx.x;

    __shared__ float s_q [K_ * D_ * D_];   // 512
    __shared__ float s_cq[K_ * D_];        // 64
    __shared__ float s_nc[K_ * D_];        // 64
    __shared__ float s_w [K_];             // 8

    {
        const float* qs = g_Q + (size_t)t * (K_ * D_ * D_);
#pragma unroll
        for (int i = tid; i < K_ * D_ * D_; i += 256) s_q[i] = qs[i];
        if (tid < 64)        s_cq[tid]       = g_cq[t * 64 + tid];
        else if (tid < 128)  s_nc[tid - 64]  = g_nc[t * 64 + (tid - 64)];
        else if (tid < 136)  s_w [tid - 128] = g_w [t * K_ + (tid - 128)];
    }
    __syncthreads();

    const int b0 = blockIdx.x * (256 * ILP) + tid;

    float xv[ILP][D_];
#pragma unroll
    for (int u = 0; u < ILP; u++) {
        int b = b0 + u * 256;
        if (b < B) {
            const float4* xp = reinterpret_cast<const float4*>(x) + ((size_t)b * T_ + t) * 2;
            float4 lo = xp[0], hi = xp[1];
            xv[u][0] = lo.x; xv[u][1] = lo.y; xv[u][2] = lo.z; xv[u][3] = lo.w;
            xv[u][4] = hi.x; xv[u][5] = hi.y; xv[u][6] = hi.z; xv[u][7] = hi.w;
        } else {
#pragma unroll
            for (int d = 0; d < D_; d++) xv[u][d] = 0.f;
        }
    }

    float p[ILP];
#pragma unroll
    for (int u = 0; u < ILP; u++) p[u] = 0.f;

#pragma unroll 1   // keep k-loop rolled: ~2KB body fits L0 I-cache
    for (int k = 0; k < K_; k++) {
        const float* qk = s_q + k * (D_ * D_);
        float acc[ILP];
#pragma unroll
        for (int u = 0; u < ILP; u++) acc[u] = 0.f;

#pragma unroll
        for (int j = 0; j < D_; j++) {
            float ncj = s_nc[k * D_ + j];
            float cqj = s_cq[k * D_ + j];
            float y[ILP];
#pragma unroll
            for (int u = 0; u < ILP; u++) y[u] = cqj;
#pragma unroll
            for (int i = 0; i < D_; i++) {
                float qv = qk[i * D_ + j];
#pragma unroll
                for (int u = 0; u < ILP; u++) y[u] = fmaf(xv[u][i], qv, y[u]);
            }
#pragma unroll
            for (int u = 0; u < ILP; u++) {
                float z = -(y[u] * y[u]);            // exponent already in base 2
                float e = ex2f(z);
                float g = fmaf(ncj, e, EPS_);        // gaussian + EPS
                acc[u] += lg2f(g);                   // sum of log2
            }
        }
        float wk = s_w[k];
#pragma unroll
        for (int u = 0; u < ILP; u++)
            p[u] = fmaf(wk, ex2f(acc[u]), p[u]);     // exp(sum ln) == 2^(sum log2)
    }

#pragma unroll
    for (int u = 0; u < ILP; u++) {
        int b = b0 + u * 256;
        if (b < B) out[(size_t)b * T_ + t] = p[u];
    }
}

// ---------------- launch ----------------
extern "C" void kernel_launch(void* const* d_in, const int* in_sizes, int n_in,
                              void* d_out, int out_size) {
    const float* x       = (const float*)d_in[0];
    const float* centers = (const float*)d_in[1];
    const float* wl      = (const float*)d_in[2];
    const float* lv      = (const float*)d_in[3];
    const float* cov     = (const float*)d_in[4];
    float* out = (float*)d_out;

    int B = in_sizes[0] / (T_ * D_);

    cayley_kernel<<<(T_ * K_ + 127) / 128, 128>>>(cov);
    params_kernel<<<(T_ * K_ + 127) / 128, 128>>>(centers, wl, lv);

    dim3 grid((B + 256 * ILP - 1) / (256 * ILP), T_);
    pdf_kernel<<<grid, 256>>>(x, out, B);
}